// round 7
// baseline (speedup 1.0000x reference)
#include <cuda_runtime.h>
#include <cuda_bf16.h>
#include <math.h>

// ---------------------------------------------------------------------------
// HybridConv: out[n] = MLP(RBF(sigmoid(dot(data[n], conv_w) + conv_b)))
// out is a smooth scalar function f of t = 2*sigmoid(logit)-1 = tanh(logit/2).
// Build kernel (ONE warp): evaluate f at 32 Chebyshev nodes (precise), DCT ->
// 24 Chebyshev coefficients (double accumulation).
// Main kernel: 4x LDG.128 -> dot -> tanh.approx(l/2) -> degree-23 Clenshaw
// with fma.rn.f32x2 (2 patches/instr) -> STG.128.  NO shared-memory table,
// no LDS conflicts: L1tex carries only the streaming LDG/STG wavefronts.
// ---------------------------------------------------------------------------

#define NCOEF 24   // Chebyshev degree 23
#define BASIS 8
#define HIDDEN 16

__device__ float g_coef[NCOEF];   // g_coef[0] is already halved (c0/2)

#define FMA2(d, a, b, c) \
    asm("fma.rn.f32x2 %0, %1, %2, %3;" \
        : "=l"(d) : "l"(a), "l"(b), "l"(c))
#define PACK2(d, lo, hi) \
    asm("mov.b64 %0, {%1, %2};" : "=l"(d) : "f"(lo), "f"(hi))
#define UNPACK2(lo, hi, s) \
    asm("mov.b64 {%0, %1}, %2;" : "=f"(lo), "=f"(hi) : "l"(s))

__device__ __forceinline__ float fast_tanh(float x) {
    float y;
    asm("tanh.approx.f32 %0, %1;" : "=f"(y) : "f"(x));
    return y;
}

// ---- build: one warp. lane j = node j; then lane k = coefficient k --------
__global__ void build_coef_kernel(const float* __restrict__ basis,
                                  const float* __restrict__ w1,
                                  const float* __restrict__ b1,
                                  const float* __restrict__ w2,
                                  const float* __restrict__ b2) {
    const int lane = threadIdx.x;            // 0..31
    const double PI = 3.14159265358979323846;

    // node value: t_j = cos(theta_j), act = (1+t)/2
    double theta_j = ((double)lane + 0.5) * (PI / 32.0);
    float a = (float)(0.5 + 0.5 * cos(theta_j));

    // f(a): RBF feats -> MLP (precise float path)
    float feats[BASIS];
#pragma unroll
    for (int j = 0; j < BASIS; j++) {
        float s = 0.0f;
#pragma unroll
        for (int k = 0; k < 4; k++) {
            float d = a - basis[j * 4 + k];
            s = fmaf(d, d, s);
        }
        feats[j] = expf(-s);                 // GAMMA = 1
    }
    float fv = b2[0];
#pragma unroll
    for (int i = 0; i < HIDDEN; i++) {
        float p = b1[i];
#pragma unroll
        for (int j = 0; j < BASIS; j++)
            p = fmaf(feats[j], w1[j * HIDDEN + i], p);
        fv = fmaf(tanhf(p), w2[i], fv);
    }

    // DCT: c_k = (2/32) sum_j f_j cos(k*theta_j); lane = k. All lanes shuffle.
    double ck = 0.0;
    for (int j = 0; j < 32; j++) {
        float fj = __shfl_sync(0xFFFFFFFFu, fv, j);
        double th = ((double)j + 0.5) * (PI / 32.0);
        ck += (double)fj * cos((double)lane * th);
    }
    ck *= (2.0 / 32.0);
    if (lane == 0) ck *= 0.5;                // store c0/2 directly
    if (lane < NCOEF) g_coef[lane] = (float)ck;
}

// ---- scalar Clenshaw (tail path only) -------------------------------------
__device__ __forceinline__ float clenshaw_scalar(float t, const float* c) {
    float b1 = c[NCOEF - 1], b2 = 0.0f, tt = t + t;
#pragma unroll
    for (int k = NCOEF - 2; k >= 1; k--) {
        float nb = fmaf(tt, b1, c[k] - b2);
        b2 = b1; b1 = nb;
    }
    return fmaf(t, b1, c[0] - b2);           // c[0] pre-halved
}

// ---- main streaming pass --------------------------------------------------
__global__ void __launch_bounds__(256)
hybridconv_main_kernel(const float4* __restrict__ data,
                       const float* __restrict__ conv_w,
                       const float* __restrict__ conv_b,
                       float4* __restrict__ out, int n4, int n) {
    float c[NCOEF];
#pragma unroll
    for (int k = 0; k < NCOEF; k++) c[k] = g_coef[k];

    const float w0 = conv_w[0], w1 = conv_w[1];
    const float w2 = conv_w[2], w3 = conv_w[3];
    const float bb = conv_b[0];

    unsigned long long negone;
    PACK2(negone, -1.0f, -1.0f);

    const int stride = gridDim.x * blockDim.x;
    int gid = blockIdx.x * blockDim.x + threadIdx.x;

    for (int i = gid; i < n4; i += stride) {
        const float4* p = data + 4 * i;
        float4 v0 = __ldcs(p + 0);
        float l0 = fmaf(v0.x, w0, fmaf(v0.y, w1, fmaf(v0.z, w2, fmaf(v0.w, w3, bb))));
        float4 v1 = __ldcs(p + 1);
        float l1 = fmaf(v1.x, w0, fmaf(v1.y, w1, fmaf(v1.z, w2, fmaf(v1.w, w3, bb))));
        float4 v2 = __ldcs(p + 2);
        float l2 = fmaf(v2.x, w0, fmaf(v2.y, w1, fmaf(v2.z, w2, fmaf(v2.w, w3, bb))));
        float4 v3 = __ldcs(p + 3);
        float l3 = fmaf(v3.x, w0, fmaf(v3.y, w1, fmaf(v3.z, w2, fmaf(v3.w, w3, bb))));

        // t = 2*sigmoid(l)-1 = tanh(l/2): one MUFU each
        float t0 = fast_tanh(0.5f * l0);
        float t1 = fast_tanh(0.5f * l1);
        float t2 = fast_tanh(0.5f * l2);
        float t3 = fast_tanh(0.5f * l3);

        unsigned long long tA, tB, ttA, ttB;
        PACK2(tA, t0, t1);
        PACK2(tB, t2, t3);
        PACK2(ttA, t0 + t0, t1 + t1);
        PACK2(ttB, t2 + t2, t3 + t3);

        // Clenshaw, two f32x2 chains (patches {0,1} and {2,3})
        unsigned long long b1A, b1B, b2A = 0ull, b2B = 0ull;
        PACK2(b1A, c[NCOEF - 1], c[NCOEF - 1]);
        b1B = b1A;
#pragma unroll
        for (int k = NCOEF - 2; k >= 1; k--) {
            unsigned long long ck2, sA, sB, nA, nB;
            PACK2(ck2, c[k], c[k]);
            FMA2(sA, b2A, negone, ck2);      // c_k - b2
            FMA2(sB, b2B, negone, ck2);
            FMA2(nA, ttA, b1A, sA);          // 2t*b1 + (c_k - b2)
            FMA2(nB, ttB, b1B, sB);
            b2A = b1A; b1A = nA;
            b2B = b1B; b1B = nB;
        }
        unsigned long long c02, sA, sB, rA, rB;
        PACK2(c02, c[0], c[0]);              // c0/2 pre-halved
        FMA2(sA, b2A, negone, c02);
        FMA2(sB, b2B, negone, c02);
        FMA2(rA, tA, b1A, sA);
        FMA2(rB, tB, b1B, sB);

        float4 r;
        UNPACK2(r.x, r.y, rA);
        UNPACK2(r.z, r.w, rB);
        __stcs(&out[i], r);
    }

    // defensive tail (empty when n % 4 == 0)
    const float* sdata = (const float*)data;
    float* sout = (float*)out;
    for (int k = 4 * n4 + gid; k < n; k += stride) {
        float4 v = ((const float4*)sdata)[k];
        float l = fmaf(v.x, w0, fmaf(v.y, w1, fmaf(v.z, w2, fmaf(v.w, w3, bb))));
        sout[k] = clenshaw_scalar(fast_tanh(0.5f * l), c);
    }
}

extern "C" void kernel_launch(void* const* d_in, const int* in_sizes, int n_in,
                              void* d_out, int out_size) {
    const float* data   = (const float*)d_in[0];   // [N, 2, 2]
    const float* conv_w = (const float*)d_in[1];   // [2, 2]
    const float* conv_b = (const float*)d_in[2];   // [1]
    const float* basis  = (const float*)d_in[3];   // [8, 4]
    const float* w1     = (const float*)d_in[4];   // [8, 16]
    const float* b1     = (const float*)d_in[5];   // [16]
    const float* w2     = (const float*)d_in[6];   // [16, 1]
    const float* b2     = (const float*)d_in[7];   // [1]

    const int n  = in_sizes[0] / 4;  // patches
    const int n4 = n / 4;

    build_coef_kernel<<<1, 32>>>(basis, w1, b1, w2, b2);

    hybridconv_main_kernel<<<1216, 256>>>(
        (const float4*)data, conv_w, conv_b, (float4*)d_out, n4, n);
}

// round 8
// speedup vs baseline: 1.8067x; 1.8067x over previous
#include <cuda_runtime.h>
#include <cuda_bf16.h>
#include <math.h>

// ---------------------------------------------------------------------------
// HybridConv: out[n] = MLP(RBF(sigmoid(dot(data[n], conv_w) + conv_b)))
// out is a smooth scalar function f of t = 2*sigmoid(logit)-1 = tanh(logit/2).
// Build kernel (ONE warp, ALL FLOAT — no fp64 trig!): evaluate f at 32
// Chebyshev nodes, DCT via cospif -> 20 Chebyshev coefficients.
// Main kernel: 4x LDG.128 -> dot -> tanh.approx(l/2) -> degree-19 Clenshaw
// with fma.rn.f32x2 (2 patches/instr) -> STG.128. No shared memory, no LDS.
// ---------------------------------------------------------------------------

#define NCOEF 20   // Chebyshev degree 19
#define BASIS 8
#define HIDDEN 16

__device__ float g_coef[NCOEF];   // g_coef[0] is already halved (c0/2)

#define FMA2(d, a, b, c) \
    asm("fma.rn.f32x2 %0, %1, %2, %3;" \
        : "=l"(d) : "l"(a), "l"(b), "l"(c))
#define PACK2(d, lo, hi) \
    asm("mov.b64 %0, {%1, %2};" : "=l"(d) : "f"(lo), "f"(hi))
#define UNPACK2(lo, hi, s) \
    asm("mov.b64 {%0, %1}, %2;" : "=f"(lo), "=f"(hi) : "l"(s))

__device__ __forceinline__ float fast_tanh(float x) {
    float y;
    asm("tanh.approx.f32 %0, %1;" : "=f"(y) : "f"(x));
    return y;
}

// ---- build: one warp, float-only. lane j = node; then lane k = coeff ------
__global__ void build_coef_kernel(const float* __restrict__ basis,
                                  const float* __restrict__ w1,
                                  const float* __restrict__ b1,
                                  const float* __restrict__ w2,
                                  const float* __restrict__ b2) {
    const int lane = threadIdx.x;            // 0..31

    // node: t_j = cos(pi*(2j+1)/64), act a = (1+t)/2  — float cospif, exact arg
    float t_node = cospif((float)(2 * lane + 1) * (1.0f / 64.0f));
    float a = 0.5f + 0.5f * t_node;

    // f(a): RBF feats -> MLP (precise float expf/tanhf)
    float feats[BASIS];
#pragma unroll
    for (int j = 0; j < BASIS; j++) {
        float s = 0.0f;
#pragma unroll
        for (int k = 0; k < 4; k++) {
            float d = a - basis[j * 4 + k];
            s = fmaf(d, d, s);
        }
        feats[j] = expf(-s);                 // GAMMA = 1
    }
    float fv = b2[0];
#pragma unroll
    for (int i = 0; i < HIDDEN; i++) {
        float p = b1[i];
#pragma unroll
        for (int j = 0; j < BASIS; j++)
            p = fmaf(feats[j], w1[j * HIDDEN + i], p);
        fv = fmaf(tanhf(p), w2[i], fv);
    }

    // DCT: c_k = (1/16) sum_j f_j cos(pi*k*(2j+1)/64); lane = k.
    // All 32 lanes run every shuffle (full-warp, no divergence).
    float ck = 0.0f;
#pragma unroll 4
    for (int j = 0; j < 32; j++) {
        float fj = __shfl_sync(0xFFFFFFFFu, fv, j);
        float w  = cospif((float)(lane * (2 * j + 1)) * (1.0f / 64.0f));
        ck = fmaf(fj, w, ck);
    }
    ck *= (1.0f / 16.0f);
    if (lane == 0) ck *= 0.5f;               // store c0/2 directly
    if (lane < NCOEF) g_coef[lane] = ck;
}

// ---- scalar Clenshaw (tail path only) -------------------------------------
__device__ __forceinline__ float clenshaw_scalar(float t, const float* c) {
    float b1 = c[NCOEF - 1], b2 = 0.0f, tt = t + t;
#pragma unroll
    for (int k = NCOEF - 2; k >= 1; k--) {
        float nb = fmaf(tt, b1, c[k] - b2);
        b2 = b1; b1 = nb;
    }
    return fmaf(t, b1, c[0] - b2);           // c[0] pre-halved
}

// ---- main streaming pass --------------------------------------------------
__global__ void __launch_bounds__(256)
hybridconv_main_kernel(const float4* __restrict__ data,
                       const float* __restrict__ conv_w,
                       const float* __restrict__ conv_b,
                       float4* __restrict__ out, int n4, int n) {
    float c[NCOEF];
#pragma unroll
    for (int k = 0; k < NCOEF; k++) c[k] = g_coef[k];

    const float w0 = conv_w[0], w1 = conv_w[1];
    const float w2 = conv_w[2], w3 = conv_w[3];
    const float bb = conv_b[0];

    unsigned long long negone;
    PACK2(negone, -1.0f, -1.0f);

    const int stride = gridDim.x * blockDim.x;
    int gid = blockIdx.x * blockDim.x + threadIdx.x;

    for (int i = gid; i < n4; i += stride) {
        const float4* p = data + 4 * i;
        float4 v0 = __ldcs(p + 0);
        float l0 = fmaf(v0.x, w0, fmaf(v0.y, w1, fmaf(v0.z, w2, fmaf(v0.w, w3, bb))));
        float4 v1 = __ldcs(p + 1);
        float l1 = fmaf(v1.x, w0, fmaf(v1.y, w1, fmaf(v1.z, w2, fmaf(v1.w, w3, bb))));
        float4 v2 = __ldcs(p + 2);
        float l2 = fmaf(v2.x, w0, fmaf(v2.y, w1, fmaf(v2.z, w2, fmaf(v2.w, w3, bb))));
        float4 v3 = __ldcs(p + 3);
        float l3 = fmaf(v3.x, w0, fmaf(v3.y, w1, fmaf(v3.z, w2, fmaf(v3.w, w3, bb))));

        // t = 2*sigmoid(l)-1 = tanh(l/2): one MUFU each
        float t0 = fast_tanh(0.5f * l0);
        float t1 = fast_tanh(0.5f * l1);
        float t2 = fast_tanh(0.5f * l2);
        float t3 = fast_tanh(0.5f * l3);

        unsigned long long tA, tB, ttA, ttB;
        PACK2(tA, t0, t1);
        PACK2(tB, t2, t3);
        PACK2(ttA, t0 + t0, t1 + t1);
        PACK2(ttB, t2 + t2, t3 + t3);

        // Clenshaw, two f32x2 chains (patches {0,1} and {2,3})
        unsigned long long b1A, b1B, b2A = 0ull, b2B = 0ull;
        PACK2(b1A, c[NCOEF - 1], c[NCOEF - 1]);
        b1B = b1A;
#pragma unroll
        for (int k = NCOEF - 2; k >= 1; k--) {
            unsigned long long ck2, sA, sB, nA, nB;
            PACK2(ck2, c[k], c[k]);
            FMA2(sA, b2A, negone, ck2);      // c_k - b2
            FMA2(sB, b2B, negone, ck2);
            FMA2(nA, ttA, b1A, sA);          // 2t*b1 + (c_k - b2)
            FMA2(nB, ttB, b1B, sB);
            b2A = b1A; b1A = nA;
            b2B = b1B; b1B = nB;
        }
        unsigned long long c02, sA, sB, rA, rB;
        PACK2(c02, c[0], c[0]);              // c0/2 pre-halved
        FMA2(sA, b2A, negone, c02);
        FMA2(sB, b2B, negone, c02);
        FMA2(rA, tA, b1A, sA);
        FMA2(rB, tB, b1B, sB);

        float4 r;
        UNPACK2(r.x, r.y, rA);
        UNPACK2(r.z, r.w, rB);
        __stcs(&out[i], r);
    }

    // defensive tail (empty when n % 4 == 0)
    const float* sdata = (const float*)data;
    float* sout = (float*)out;
    for (int k = 4 * n4 + gid; k < n; k += stride) {
        float4 v = ((const float4*)sdata)[k];
        float l = fmaf(v.x, w0, fmaf(v.y, w1, fmaf(v.z, w2, fmaf(v.w, w3, bb))));
        sout[k] = clenshaw_scalar(fast_tanh(0.5f * l), c);
    }
}

extern "C" void kernel_launch(void* const* d_in, const int* in_sizes, int n_in,
                              void* d_out, int out_size) {
    const float* data   = (const float*)d_in[0];   // [N, 2, 2]
    const float* conv_w = (const float*)d_in[1];   // [2, 2]
    const float* conv_b = (const float*)d_in[2];   // [1]
    const float* basis  = (const float*)d_in[3];   // [8, 4]
    const float* w1     = (const float*)d_in[4];   // [8, 16]
    const float* b1     = (const float*)d_in[5];   // [16]
    const float* w2     = (const float*)d_in[6];   // [16, 1]
    const float* b2     = (const float*)d_in[7];   // [1]

    const int n  = in_sizes[0] / 4;  // patches
    const int n4 = n / 4;

    build_coef_kernel<<<1, 32>>>(basis, w1, b1, w2, b2);

    hybridconv_main_kernel<<<1216, 256>>>(
        (const float4*)data, conv_w, conv_b, (float4*)d_out, n4, n);
}